// round 1
// baseline (speedup 1.0000x reference)
#include <cuda_runtime.h>
#include <math.h>

#define BB 2
#define SS 2048
#define DD 1024
#define HH 16
#define DKK 64
#define MM (BB*SS)

// Scratch (allocation-free rule: __device__ globals)
__device__ float g_Q[(size_t)MM * DD];
__device__ float g_K[(size_t)MM * DD];
__device__ float g_V[(size_t)MM * DD];
__device__ float g_ctx[(size_t)MM * DD];

// ---------------------------------------------------------------------------
// GEMM: C[M,N] = A[M,K] @ W[K,N] + bias[N]
// 64x64 block tile, BK=16, 256 threads, 4x4 micro-tile.
// A tile stored transposed in SMEM with XOR swizzle (col ^= 4k) so the
// transpose scalar-stores are ~conflict-free and the float4 reads stay aligned.
// ---------------------------------------------------------------------------
__global__ void __launch_bounds__(256) gemm_bias_kernel(
    const float* __restrict__ A, const float* __restrict__ W,
    const float* __restrict__ bias, float* __restrict__ C,
    int M, int N, int K)
{
    __shared__ float Ats[16][64];   // Ats[k][ m ^ (4k & 63) ]
    __shared__ float Ws[16][64];

    const int tid = threadIdx.x;
    const int tx = tid & 15, ty = tid >> 4;
    const int row0 = blockIdx.y * 64, col0 = blockIdx.x * 64;

    // A load mapping: row am (0..63), float4 slot kq (0..3) inside BK=16
    const int am = tid >> 2, kq = tid & 3;
    const float* Ap = A + (size_t)(row0 + am) * K + kq * 4;
    const float* Wp = W + (size_t)ty * N + col0 + tx * 4;

    float acc[4][4] = {};

    float4 av = *(const float4*)Ap;
    float4 wv = *(const float4*)Wp;

    for (int k0 = 0; k0 < K; k0 += 16) {
        // store current tile
        {
            const int kb = 4 * kq;
            Ats[kb + 0][am ^ ((4 * (kb + 0)) & 63)] = av.x;
            Ats[kb + 1][am ^ ((4 * (kb + 1)) & 63)] = av.y;
            Ats[kb + 2][am ^ ((4 * (kb + 2)) & 63)] = av.z;
            Ats[kb + 3][am ^ ((4 * (kb + 3)) & 63)] = av.w;
        }
        *(float4*)&Ws[ty][tx * 4] = wv;
        __syncthreads();

        // prefetch next tile (overlap with compute)
        if (k0 + 16 < K) {
            av = *(const float4*)(Ap + k0 + 16);
            wv = *(const float4*)(Wp + (size_t)(k0 + 16) * N);
        }

        #pragma unroll
        for (int kk = 0; kk < 16; kk++) {
            float4 a = *(float4*)&Ats[kk][(4 * ty) ^ ((4 * kk) & 63)];
            float4 b = *(float4*)&Ws[kk][4 * tx];
            float aa[4] = {a.x, a.y, a.z, a.w};
            float bb[4] = {b.x, b.y, b.z, b.w};
            #pragma unroll
            for (int i = 0; i < 4; i++)
                #pragma unroll
                for (int j = 0; j < 4; j++)
                    acc[i][j] += aa[i] * bb[j];
        }
        __syncthreads();
    }

    float4 bv = *(const float4*)(bias + col0 + 4 * tx);
    float bb4[4] = {bv.x, bv.y, bv.z, bv.w};
    #pragma unroll
    for (int i = 0; i < 4; i++) {
        float4 o;
        o.x = acc[i][0] + bb4[0];
        o.y = acc[i][1] + bb4[1];
        o.z = acc[i][2] + bb4[2];
        o.w = acc[i][3] + bb4[3];
        *(float4*)&C[(size_t)(row0 + 4 * ty + i) * N + col0 + 4 * tx] = o;
    }
}

// ---------------------------------------------------------------------------
// Flash attention: one CTA = one (b, h, 64-row q-tile). 256 threads, 4x4.
// SMEM: Qt[d][r] (transposed, pre-scaled), KPs = Kt[d][c] reused as Ps[r][c],
// Vs[c][d]. 48 KB exactly.
// ---------------------------------------------------------------------------
__global__ void __launch_bounds__(256) attn_kernel()
{
    __shared__ float Qt [64 * 64];
    __shared__ float KPs[64 * 64];
    __shared__ float Vs [64 * 64];

    const int tid = threadIdx.x;
    const int tx = tid & 15, ty = tid >> 4;
    const int qt = blockIdx.x;
    const int b  = blockIdx.y >> 4;
    const int h  = blockIdx.y & 15;

    const size_t base = (size_t)(b * SS) * DD + (size_t)h * DKK;
    const float* Qg = g_Q + base;
    const float* Kg = g_K + base;
    const float* Vg = g_V + base;

    // Load Q tile transposed + pre-scaled by 1/sqrt(dk)=0.125.
    // Lane-fastest-row mapping -> conflict-free transpose stores.
    {
        const int r = tid & 63, fq = tid >> 6;
        #pragma unroll
        for (int g2 = 0; g2 < 4; g2++) {
            const int f = fq * 4 + g2;
            float4 qv = *(const float4*)(Qg + (size_t)(qt * 64 + r) * DD + 4 * f);
            Qt[(4 * f + 0) * 64 + r] = qv.x * 0.125f;
            Qt[(4 * f + 1) * 64 + r] = qv.y * 0.125f;
            Qt[(4 * f + 2) * 64 + r] = qv.z * 0.125f;
            Qt[(4 * f + 3) * 64 + r] = qv.w * 0.125f;
        }
    }

    float o[4][4] = {};
    float mrow[4] = {-1e30f, -1e30f, -1e30f, -1e30f};
    float lrow[4] = {};

    for (int kt = 0; kt < SS / 64; kt++) {
        __syncthreads();   // prev PV reads done (also orders Q stores on iter 0)

        // K tile -> transposed Kt[d][c] (conflict-free scalar stores)
        {
            const int c = tid & 63, fq = tid >> 6;
            #pragma unroll
            for (int g2 = 0; g2 < 4; g2++) {
                const int f = fq * 4 + g2;
                float4 kv = *(const float4*)(Kg + (size_t)(kt * 64 + c) * DD + 4 * f);
                KPs[(4 * f + 0) * 64 + c] = kv.x;
                KPs[(4 * f + 1) * 64 + c] = kv.y;
                KPs[(4 * f + 2) * 64 + c] = kv.z;
                KPs[(4 * f + 3) * 64 + c] = kv.w;
            }
        }
        // V tile direct copy Vs[c][d]
        #pragma unroll
        for (int it = 0; it < 4; it++) {
            const int idx = tid + it * 256;
            const int c = idx >> 4, f = idx & 15;
            float4 vv = *(const float4*)(Vg + (size_t)(kt * 64 + c) * DD + 4 * f);
            *(float4*)&Vs[c * 64 + 4 * f] = vv;
        }
        __syncthreads();

        // S = (Q*scale) @ K^T  -- 64-deep rank-1 updates from SMEM
        float s[4][4] = {};
        #pragma unroll 8
        for (int d = 0; d < 64; d++) {
            float4 a = *(float4*)&Qt [d * 64 + 4 * ty];
            float4 k4 = *(float4*)&KPs[d * 64 + 4 * tx];
            float aa[4] = {a.x, a.y, a.z, a.w};
            float kk[4] = {k4.x, k4.y, k4.z, k4.w};
            #pragma unroll
            for (int i = 0; i < 4; i++)
                #pragma unroll
                for (int j = 0; j < 4; j++)
                    s[i][j] += aa[i] * kk[j];
        }

        // Online softmax (rows shared by the 16 lanes of a tx-group)
        float p[4][4];
        #pragma unroll
        for (int i = 0; i < 4; i++) {
            float tm = fmaxf(fmaxf(s[i][0], s[i][1]), fmaxf(s[i][2], s[i][3]));
            #pragma unroll
            for (int off = 8; off >= 1; off >>= 1)
                tm = fmaxf(tm, __shfl_xor_sync(0xffffffffu, tm, off));
            const float mn   = fmaxf(mrow[i], tm);
            const float corr = __expf(mrow[i] - mn);
            mrow[i] = mn;
            float rs = 0.f;
            #pragma unroll
            for (int j = 0; j < 4; j++) {
                p[i][j] = __expf(s[i][j] - mn);
                rs += p[i][j];
            }
            #pragma unroll
            for (int off = 8; off >= 1; off >>= 1)
                rs += __shfl_xor_sync(0xffffffffu, rs, off);
            lrow[i] = lrow[i] * corr + rs;
            #pragma unroll
            for (int j = 0; j < 4; j++) o[i][j] *= corr;
        }

        __syncthreads();   // all Kt reads done before overwriting with P

        // Store P row-major with XOR swizzle on the column group
        #pragma unroll
        for (int i = 0; i < 4; i++) {
            const int r = 4 * ty + i;
            *(float4*)&KPs[r * 64 + ((4 * tx) ^ ((4 * r) & 63))] =
                make_float4(p[i][0], p[i][1], p[i][2], p[i][3]);
        }
        __syncthreads();

        // O += P @ V
        #pragma unroll 8
        for (int c = 0; c < 64; c++) {
            float4 v = *(float4*)&Vs[c * 64 + 4 * tx];
            float vv4[4] = {v.x, v.y, v.z, v.w};
            #pragma unroll
            for (int i = 0; i < 4; i++) {
                const int r = 4 * ty + i;
                const float pi = KPs[r * 64 + (c ^ ((4 * r) & 63))];
                #pragma unroll
                for (int j = 0; j < 4; j++) o[i][j] += pi * vv4[j];
            }
        }
    }

    // Normalize and write context (heads interleaved back to [B,S,D])
    #pragma unroll
    for (int i = 0; i < 4; i++) {
        const float inv = 1.f / lrow[i];
        float4 ov = make_float4(o[i][0] * inv, o[i][1] * inv,
                                o[i][2] * inv, o[i][3] * inv);
        *(float4*)&g_ctx[(size_t)(b * SS + qt * 64 + 4 * ty + i) * DD
                         + (size_t)h * DKK + 4 * tx] = ov;
    }
}

// ---------------------------------------------------------------------------
extern "C" void kernel_launch(void* const* d_in, const int* in_sizes, int n_in,
                              void* d_out, int out_size)
{
    (void)in_sizes; (void)n_in; (void)out_size;
    const float* q  = (const float*)d_in[0];
    const float* k  = (const float*)d_in[1];
    const float* v  = (const float*)d_in[2];
    const float* wq = (const float*)d_in[3];
    const float* bq = (const float*)d_in[4];
    const float* wk = (const float*)d_in[5];
    const float* bk = (const float*)d_in[6];
    const float* wv = (const float*)d_in[7];
    const float* bv = (const float*)d_in[8];
    const float* wo = (const float*)d_in[9];
    const float* bo = (const float*)d_in[10];
    float* out = (float*)d_out;

    float *gq, *gk, *gv, *gctx;
    cudaGetSymbolAddress((void**)&gq,   g_Q);
    cudaGetSymbolAddress((void**)&gk,   g_K);
    cudaGetSymbolAddress((void**)&gv,   g_V);
    cudaGetSymbolAddress((void**)&gctx, g_ctx);

    dim3 ggrid(DD / 64, MM / 64);   // (16, 64)
    gemm_bias_kernel<<<ggrid, 256>>>(q, wq, bq, gq, MM, DD, DD);
    gemm_bias_kernel<<<ggrid, 256>>>(k, wk, bk, gk, MM, DD, DD);
    gemm_bias_kernel<<<ggrid, 256>>>(v, wv, bv, gv, MM, DD, DD);

    attn_kernel<<<dim3(SS / 64, BB * HH), 256>>>();

    gemm_bias_kernel<<<ggrid, 256>>>(gctx, wo, bo, out, MM, DD, DD);
}

// round 2
// speedup vs baseline: 2.9791x; 2.9791x over previous
#include <cuda_runtime.h>
#include <math.h>
#include <stdint.h>

#define BB 2
#define SS 2048
#define DD 1024
#define HH 16
#define DKK 64
#define MM (BB*SS)

// Scratch (allocation-free rule: __device__ globals)
__device__ float g_Q[(size_t)MM * DD];
__device__ float g_K[(size_t)MM * DD];
__device__ float g_V[(size_t)MM * DD];
__device__ float g_ctx[(size_t)MM * DD];

__device__ __forceinline__ uint32_t f2tf(float f) {
    uint32_t u; asm("cvt.rna.tf32.f32 %0, %1;" : "=r"(u) : "f"(f)); return u;
}

// D += A(16x8) * B(8x8), tf32 inputs, fp32 accum
__device__ __forceinline__ void mma8(float* d, const uint32_t* a, const uint32_t* b) {
    asm volatile(
        "mma.sync.aligned.m16n8k8.row.col.f32.tf32.tf32.f32 "
        "{%0,%1,%2,%3}, {%4,%5,%6,%7}, {%8,%9}, {%0,%1,%2,%3};\n"
        : "+f"(d[0]), "+f"(d[1]), "+f"(d[2]), "+f"(d[3])
        : "r"(a[0]), "r"(a[1]), "r"(a[2]), "r"(a[3]), "r"(b[0]), "r"(b[1]));
}

// ---------------------------------------------------------------------------
// GEMM: C[M,N] = A[M,K] @ W[K,N] + bias.  Tensor-core tf32.
// Block 128x64, BK=32, 256 threads = 8 warps of 32x32.
// Pads: As rows of 36 (bank = 4m+k distinct), Bs rows of 72 (bank = 8k+n).
// ---------------------------------------------------------------------------
#define GPA 36
#define GPB 72

__global__ void __launch_bounds__(256) gemm_tc(
    const float* __restrict__ A, const float* __restrict__ W,
    const float* __restrict__ bias, float* __restrict__ C,
    int M, int N, int K)
{
    __shared__ uint32_t As[128 * GPA];
    __shared__ uint32_t Bs[32 * GPB];

    const int tid  = threadIdx.x;
    const int lane = tid & 31, warp = tid >> 5;
    const int g = lane >> 2, tig = lane & 3;
    const int wm = warp >> 1, wn = warp & 1;
    const int row0 = blockIdx.y * 128, col0 = blockIdx.x * 64;

    // global->smem mappings
    const int rA = tid >> 3, cA = (tid & 7) * 4;     // + 32*i rows, i=0..3
    const int rB = tid >> 4, cB = (tid & 15) * 4;    // + 16*i rows, i=0..1
    const float* Ap = A + (size_t)(row0 + rA) * K + cA;
    const float* Wp = W + (size_t)rB * N + col0 + cB;

    float acc[2][4][4] = {};
    float4 av[4], wv[2];

    #pragma unroll
    for (int i = 0; i < 4; i++) av[i] = *(const float4*)(Ap + (size_t)(32 * i) * K);
    #pragma unroll
    for (int i = 0; i < 2; i++) wv[i] = *(const float4*)(Wp + (size_t)(16 * i) * N);

    for (int k0 = 0; k0 < K; k0 += 32) {
        #pragma unroll
        for (int i = 0; i < 4; i++) {
            uint4 t = make_uint4(f2tf(av[i].x), f2tf(av[i].y), f2tf(av[i].z), f2tf(av[i].w));
            *(uint4*)&As[(rA + 32 * i) * GPA + cA] = t;
        }
        #pragma unroll
        for (int i = 0; i < 2; i++) {
            uint4 t = make_uint4(f2tf(wv[i].x), f2tf(wv[i].y), f2tf(wv[i].z), f2tf(wv[i].w));
            *(uint4*)&Bs[(rB + 16 * i) * GPB + cB] = t;
        }
        __syncthreads();

        if (k0 + 32 < K) {
            #pragma unroll
            for (int i = 0; i < 4; i++)
                av[i] = *(const float4*)(Ap + k0 + 32 + (size_t)(32 * i) * K);
            #pragma unroll
            for (int i = 0; i < 2; i++)
                wv[i] = *(const float4*)(Wp + (size_t)(k0 + 32 + 16 * i) * N);
        }

        #pragma unroll
        for (int kk = 0; kk < 4; kk++) {
            const int kb = kk * 8;
            uint32_t af[2][4], bf[4][2];
            #pragma unroll
            for (int mt = 0; mt < 2; mt++) {
                const int r = wm * 32 + mt * 16 + g;
                af[mt][0] = As[r * GPA + kb + tig];
                af[mt][1] = As[(r + 8) * GPA + kb + tig];
                af[mt][2] = As[r * GPA + kb + tig + 4];
                af[mt][3] = As[(r + 8) * GPA + kb + tig + 4];
            }
            #pragma unroll
            for (int j = 0; j < 4; j++) {
                const int n = wn * 32 + j * 8 + g;
                bf[j][0] = Bs[(kb + tig) * GPB + n];
                bf[j][1] = Bs[(kb + tig + 4) * GPB + n];
            }
            #pragma unroll
            for (int mt = 0; mt < 2; mt++)
                #pragma unroll
                for (int j = 0; j < 4; j++)
                    mma8(acc[mt][j], af[mt], bf[j]);
        }
        __syncthreads();
    }

    // epilogue: bias + store (float2, quad lanes cover 8 consecutive cols)
    #pragma unroll
    for (int mt = 0; mt < 2; mt++) {
        #pragma unroll
        for (int j = 0; j < 4; j++) {
            const int n = col0 + wn * 32 + j * 8 + 2 * tig;
            const float b0 = bias[n], b1 = bias[n + 1];
            const int r = row0 + wm * 32 + mt * 16 + g;
            float2 o0 = make_float2(acc[mt][j][0] + b0, acc[mt][j][1] + b1);
            float2 o1 = make_float2(acc[mt][j][2] + b0, acc[mt][j][3] + b1);
            *(float2*)&C[(size_t)r * N + n]       = o0;
            *(float2*)&C[(size_t)(r + 8) * N + n] = o1;
        }
    }
}

// ---------------------------------------------------------------------------
// Flash attention, tensor-core tf32.
// CTA = (128-row q-tile, b, h). 256 threads = 8 warps x 16 q-rows.
// SMEM (dynamic, 72 KB): Ks[64][72] dk-major, Vs[64][72] key-major,
// Ps[128][72] (doubles as fp32 Q staging in prologue).
// ---------------------------------------------------------------------------
#define APK 72

__global__ void __launch_bounds__(256) attn_tc()
{
    extern __shared__ uint32_t smem_u[];
    uint32_t* Ks = smem_u;                 // [64][APK]
    uint32_t* Vs = smem_u + 64 * APK;      // [64][APK]
    uint32_t* Ps = smem_u + 128 * APK;     // [128][APK]
    float*   Qst = (float*)Ps;

    const int tid  = threadIdx.x;
    const int lane = tid & 31, warp = tid >> 5;
    const int g = lane >> 2, tig = lane & 3;
    const int qt = blockIdx.x;
    const int b  = blockIdx.y >> 4;
    const int h  = blockIdx.y & 15;

    const float* Qg = g_Q + (size_t)(b * SS + qt * 128) * DD + h * 64;
    const float* Kg = g_K + (size_t)(b * SS) * DD + h * 64;
    const float* Vg = g_V + (size_t)(b * SS) * DD + h * 64;

    // ---- stage Q (scaled) then load persistent A-fragments ----
    {
        const int r = tid >> 4, c = (tid & 15) * 4;
        #pragma unroll
        for (int i = 0; i < 8; i++) {
            float4 qv = *(const float4*)(Qg + (size_t)(r + 16 * i) * DD + c);
            qv.x *= 0.125f; qv.y *= 0.125f; qv.z *= 0.125f; qv.w *= 0.125f;
            *(float4*)&Qst[(r + 16 * i) * APK + c] = qv;
        }
    }
    __syncthreads();

    const int qrow = warp * 16 + g;
    uint32_t qa[8][4];
    #pragma unroll
    for (int kt8 = 0; kt8 < 8; kt8++) {
        qa[kt8][0] = f2tf(Qst[qrow * APK + kt8 * 8 + tig]);
        qa[kt8][1] = f2tf(Qst[(qrow + 8) * APK + kt8 * 8 + tig]);
        qa[kt8][2] = f2tf(Qst[qrow * APK + kt8 * 8 + tig + 4]);
        qa[kt8][3] = f2tf(Qst[(qrow + 8) * APK + kt8 * 8 + tig + 4]);
    }

    float of[8][4] = {};
    float mrow[2] = {-1e30f, -1e30f};
    float lrow[2] = {0.f, 0.f};

    for (int kt = 0; kt < SS / 64; kt++) {
        __syncthreads();   // prev S/PV reads of Ks/Vs/Ps complete

        // K tile -> Ks[dk][key] (transposed), tf32
        {
            const float* Kt = Kg + (size_t)(kt * 64) * DD;
            const int ck = tid & 63, fq = tid >> 6;
            #pragma unroll
            for (int g2 = 0; g2 < 4; g2++) {
                const int f = fq * 4 + g2;
                float4 kv = *(const float4*)(Kt + (size_t)ck * DD + 4 * f);
                Ks[(4 * f + 0) * APK + ck] = f2tf(kv.x);
                Ks[(4 * f + 1) * APK + ck] = f2tf(kv.y);
                Ks[(4 * f + 2) * APK + ck] = f2tf(kv.z);
                Ks[(4 * f + 3) * APK + ck] = f2tf(kv.w);
            }
        }
        // V tile -> Vs[key][dk], tf32
        {
            const float* Vt = Vg + (size_t)(kt * 64) * DD;
            const int rv = tid >> 4, cv = (tid & 15) * 4;
            #pragma unroll
            for (int i = 0; i < 4; i++) {
                float4 vv = *(const float4*)(Vt + (size_t)(rv + 16 * i) * DD + cv);
                uint4 t = make_uint4(f2tf(vv.x), f2tf(vv.y), f2tf(vv.z), f2tf(vv.w));
                *(uint4*)&Vs[(rv + 16 * i) * APK + cv] = t;
            }
        }
        __syncthreads();

        // ---- S = Qs @ K^T ----
        float sf[8][4] = {};
        #pragma unroll
        for (int j = 0; j < 8; j++) {
            #pragma unroll
            for (int kt8 = 0; kt8 < 8; kt8++) {
                uint32_t bb[2];
                const int kr = kt8 * 8 + tig, nc = j * 8 + g;
                bb[0] = Ks[kr * APK + nc];
                bb[1] = Ks[(kr + 4) * APK + nc];
                mma8(sf[j], qa[kt8], bb);
            }
        }

        // ---- online softmax on C-fragments (rows g and g+8) ----
        float corr[2];
        #pragma unroll
        for (int i = 0; i < 2; i++) {
            float mx = -1e30f;
            #pragma unroll
            for (int j = 0; j < 8; j++)
                mx = fmaxf(mx, fmaxf(sf[j][2 * i], sf[j][2 * i + 1]));
            mx = fmaxf(mx, __shfl_xor_sync(0xffffffffu, mx, 1));
            mx = fmaxf(mx, __shfl_xor_sync(0xffffffffu, mx, 2));
            const float mn = fmaxf(mrow[i], mx);
            corr[i] = __expf(mrow[i] - mn);
            mrow[i] = mn;
            float rs = 0.f;
            #pragma unroll
            for (int j = 0; j < 8; j++) {
                sf[j][2 * i]     = __expf(sf[j][2 * i] - mn);
                sf[j][2 * i + 1] = __expf(sf[j][2 * i + 1] - mn);
                rs += sf[j][2 * i] + sf[j][2 * i + 1];
            }
            rs += __shfl_xor_sync(0xffffffffu, rs, 1);
            rs += __shfl_xor_sync(0xffffffffu, rs, 2);
            lrow[i] = lrow[i] * corr[i] + rs;
        }
        #pragma unroll
        for (int j = 0; j < 8; j++) {
            of[j][0] *= corr[0]; of[j][1] *= corr[0];
            of[j][2] *= corr[1]; of[j][3] *= corr[1];
        }

        // ---- P -> Ps (tf32) ----
        #pragma unroll
        for (int j = 0; j < 8; j++) {
            uint2 p01 = make_uint2(f2tf(sf[j][0]), f2tf(sf[j][1]));
            uint2 p23 = make_uint2(f2tf(sf[j][2]), f2tf(sf[j][3]));
            *(uint2*)&Ps[qrow * APK + j * 8 + 2 * tig]       = p01;
            *(uint2*)&Ps[(qrow + 8) * APK + j * 8 + 2 * tig] = p23;
        }
        __syncthreads();

        // ---- O += P @ V ----
        #pragma unroll
        for (int kt8 = 0; kt8 < 8; kt8++) {
            uint32_t pa[4];
            pa[0] = Ps[qrow * APK + kt8 * 8 + tig];
            pa[1] = Ps[(qrow + 8) * APK + kt8 * 8 + tig];
            pa[2] = Ps[qrow * APK + kt8 * 8 + tig + 4];
            pa[3] = Ps[(qrow + 8) * APK + kt8 * 8 + tig + 4];
            #pragma unroll
            for (int j = 0; j < 8; j++) {
                uint32_t bb[2];
                const int vr = kt8 * 8 + tig, nc = j * 8 + g;
                bb[0] = Vs[vr * APK + nc];
                bb[1] = Vs[(vr + 4) * APK + nc];
                mma8(of[j], pa, bb);
            }
        }
    }

    // ---- normalize + write context ----
    const float inv0 = 1.f / lrow[0], inv1 = 1.f / lrow[1];
    const size_t orow = (size_t)(b * SS + qt * 128 + qrow);
    #pragma unroll
    for (int j = 0; j < 8; j++) {
        const int n = h * 64 + j * 8 + 2 * tig;
        *(float2*)&g_ctx[orow * DD + n] =
            make_float2(of[j][0] * inv0, of[j][1] * inv0);
        *(float2*)&g_ctx[(orow + 8) * DD + n] =
            make_float2(of[j][2] * inv1, of[j][3] * inv1);
    }
}

// ---------------------------------------------------------------------------
extern "C" void kernel_launch(void* const* d_in, const int* in_sizes, int n_in,
                              void* d_out, int out_size)
{
    (void)in_sizes; (void)n_in; (void)out_size;
    const float* q  = (const float*)d_in[0];
    const float* k  = (const float*)d_in[1];
    const float* v  = (const float*)d_in[2];
    const float* wq = (const float*)d_in[3];
    const float* bq = (const float*)d_in[4];
    const float* wk = (const float*)d_in[5];
    const float* bk = (const float*)d_in[6];
    const float* wv = (const float*)d_in[7];
    const float* bv = (const float*)d_in[8];
    const float* wo = (const float*)d_in[9];
    const float* bo = (const float*)d_in[10];
    float* out = (float*)d_out;

    float *gq, *gk, *gv, *gctx;
    cudaGetSymbolAddress((void**)&gq,   g_Q);
    cudaGetSymbolAddress((void**)&gk,   g_K);
    cudaGetSymbolAddress((void**)&gv,   g_V);
    cudaGetSymbolAddress((void**)&gctx, g_ctx);

    const int ATTN_SMEM = 256 * APK * 4;   // 73728 B
    cudaFuncSetAttribute(attn_tc, cudaFuncAttributeMaxDynamicSharedMemorySize, ATTN_SMEM);

    dim3 ggrid(DD / 64, MM / 128);   // (16, 32) = 512 CTAs
    gemm_tc<<<ggrid, 256>>>(q, wq, bq, gq, MM, DD, DD);
    gemm_tc<<<ggrid, 256>>>(k, wk, bk, gk, MM, DD, DD);
    gemm_tc<<<ggrid, 256>>>(v, wv, bv, gv, MM, DD, DD);

    attn_tc<<<dim3(SS / 128, BB * HH), 256, ATTN_SMEM>>>();

    gemm_tc<<<ggrid, 256>>>(gctx, wo, bo, out, MM, DD, DD);
}

// round 3
// speedup vs baseline: 2.9820x; 1.0010x over previous
#include <cuda_runtime.h>
#include <math.h>
#include <stdint.h>

#define BB 2
#define SS 2048
#define DD 1024
#define HH 16
#define DKK 64
#define MM (BB*SS)

// Scratch (allocation-free rule: __device__ globals)
__device__ float g_Q[(size_t)MM * DD];
__device__ float g_K[(size_t)MM * DD];
__device__ float g_V[(size_t)MM * DD];
__device__ float g_ctx[(size_t)MM * DD];

__device__ __forceinline__ uint32_t f2tf(float f) {
    uint32_t u; asm("cvt.rna.tf32.f32 %0, %1;" : "=r"(u) : "f"(f)); return u;
}

// D += A(16x8) * B(8x8), tf32 inputs, fp32 accum
__device__ __forceinline__ void mma8(float* d, const uint32_t* a, const uint32_t* b) {
    asm volatile(
        "mma.sync.aligned.m16n8k8.row.col.f32.tf32.tf32.f32 "
        "{%0,%1,%2,%3}, {%4,%5,%6,%7}, {%8,%9}, {%0,%1,%2,%3};\n"
        : "+f"(d[0]), "+f"(d[1]), "+f"(d[2]), "+f"(d[3])
        : "r"(a[0]), "r"(a[1]), "r"(a[2]), "r"(a[3]), "r"(b[0]), "r"(b[1]));
}

// ---------------------------------------------------------------------------
// GEMM: C[M,N] = A[M,K] @ W[K,N] + bias.  Tensor-core tf32.
// Block 128x64, BK=32, 256 threads = 8 warps of 32x32.
// Pads: As rows of 36 (bank = 4m+k distinct), Bs rows of 72 (bank = 8k+n).
// ---------------------------------------------------------------------------
#define GPA 36
#define GPB 72

__global__ void __launch_bounds__(256) gemm_tc(
    const float* __restrict__ A, const float* __restrict__ W,
    const float* __restrict__ bias, float* __restrict__ C,
    int M, int N, int K)
{
    __shared__ uint32_t As[128 * GPA];
    __shared__ uint32_t Bs[32 * GPB];

    const int tid  = threadIdx.x;
    const int lane = tid & 31, warp = tid >> 5;
    const int g = lane >> 2, tig = lane & 3;
    const int wm = warp >> 1, wn = warp & 1;
    const int row0 = blockIdx.y * 128, col0 = blockIdx.x * 64;

    // global->smem mappings
    const int rA = tid >> 3, cA = (tid & 7) * 4;     // + 32*i rows, i=0..3
    const int rB = tid >> 4, cB = (tid & 15) * 4;    // + 16*i rows, i=0..1
    const float* Ap = A + (size_t)(row0 + rA) * K + cA;
    const float* Wp = W + (size_t)rB * N + col0 + cB;

    float acc[2][4][4] = {};
    float4 av[4], wv[2];

    #pragma unroll
    for (int i = 0; i < 4; i++) av[i] = *(const float4*)(Ap + (size_t)(32 * i) * K);
    #pragma unroll
    for (int i = 0; i < 2; i++) wv[i] = *(const float4*)(Wp + (size_t)(16 * i) * N);

    for (int k0 = 0; k0 < K; k0 += 32) {
        #pragma unroll
        for (int i = 0; i < 4; i++) {
            uint4 t = make_uint4(f2tf(av[i].x), f2tf(av[i].y), f2tf(av[i].z), f2tf(av[i].w));
            *(uint4*)&As[(rA + 32 * i) * GPA + cA] = t;
        }
        #pragma unroll
        for (int i = 0; i < 2; i++) {
            uint4 t = make_uint4(f2tf(wv[i].x), f2tf(wv[i].y), f2tf(wv[i].z), f2tf(wv[i].w));
            *(uint4*)&Bs[(rB + 16 * i) * GPB + cB] = t;
        }
        __syncthreads();

        if (k0 + 32 < K) {
            #pragma unroll
            for (int i = 0; i < 4; i++)
                av[i] = *(const float4*)(Ap + k0 + 32 + (size_t)(32 * i) * K);
            #pragma unroll
            for (int i = 0; i < 2; i++)
                wv[i] = *(const float4*)(Wp + (size_t)(k0 + 32 + 16 * i) * N);
        }

        #pragma unroll
        for (int kk = 0; kk < 4; kk++) {
            const int kb = kk * 8;
            uint32_t af[2][4], bf[4][2];
            #pragma unroll
            for (int mt = 0; mt < 2; mt++) {
                const int r = wm * 32 + mt * 16 + g;
                af[mt][0] = As[r * GPA + kb + tig];
                af[mt][1] = As[(r + 8) * GPA + kb + tig];
                af[mt][2] = As[r * GPA + kb + tig + 4];
                af[mt][3] = As[(r + 8) * GPA + kb + tig + 4];
            }
            #pragma unroll
            for (int j = 0; j < 4; j++) {
                const int n = wn * 32 + j * 8 + g;
                bf[j][0] = Bs[(kb + tig) * GPB + n];
                bf[j][1] = Bs[(kb + tig + 4) * GPB + n];
            }
            #pragma unroll
            for (int mt = 0; mt < 2; mt++)
                #pragma unroll
                for (int j = 0; j < 4; j++)
                    mma8(acc[mt][j], af[mt], bf[j]);
        }
        __syncthreads();
    }

    // epilogue: bias + store (float2, quad lanes cover 8 consecutive cols)
    #pragma unroll
    for (int mt = 0; mt < 2; mt++) {
        #pragma unroll
        for (int j = 0; j < 4; j++) {
            const int n = col0 + wn * 32 + j * 8 + 2 * tig;
            const float b0 = bias[n], b1 = bias[n + 1];
            const int r = row0 + wm * 32 + mt * 16 + g;
            float2 o0 = make_float2(acc[mt][j][0] + b0, acc[mt][j][1] + b1);
            float2 o1 = make_float2(acc[mt][j][2] + b0, acc[mt][j][3] + b1);
            *(float2*)&C[(size_t)r * N + n]       = o0;
            *(float2*)&C[(size_t)(r + 8) * N + n] = o1;
        }
    }
}

// ---------------------------------------------------------------------------
// Flash attention, tensor-core tf32.
// CTA = (128-row q-tile, b, h). 256 threads = 8 warps x 16 q-rows.
// SMEM (dynamic, 72 KB): Ks[64][72] dk-major, Vs[64][72] key-major,
// Ps[128][72] (doubles as fp32 Q staging in prologue).
// ---------------------------------------------------------------------------
#define APK 72

__global__ void __launch_bounds__(256) attn_tc()
{
    extern __shared__ uint32_t smem_u[];
    uint32_t* Ks = smem_u;                 // [64][APK]
    uint32_t* Vs = smem_u + 64 * APK;      // [64][APK]
    uint32_t* Ps = smem_u + 128 * APK;     // [128][APK]
    float*   Qst = (float*)Ps;

    const int tid  = threadIdx.x;
    const int lane = tid & 31, warp = tid >> 5;
    const int g = lane >> 2, tig = lane & 3;
    const int qt = blockIdx.x;
    const int b  = blockIdx.y >> 4;
    const int h  = blockIdx.y & 15;

    const float* Qg = g_Q + (size_t)(b * SS + qt * 128) * DD + h * 64;
    const float* Kg = g_K + (size_t)(b * SS) * DD + h * 64;
    const float* Vg = g_V + (size_t)(b * SS) * DD + h * 64;

    // ---- stage Q (scaled) then load persistent A-fragments ----
    {
        const int r = tid >> 4, c = (tid & 15) * 4;
        #pragma unroll
        for (int i = 0; i < 8; i++) {
            float4 qv = *(const float4*)(Qg + (size_t)(r + 16 * i) * DD + c);
            qv.x *= 0.125f; qv.y *= 0.125f; qv.z *= 0.125f; qv.w *= 0.125f;
            *(float4*)&Qst[(r + 16 * i) * APK + c] = qv;
        }
    }
    __syncthreads();

    const int qrow = warp * 16 + g;
    uint32_t qa[8][4];
    #pragma unroll
    for (int kt8 = 0; kt8 < 8; kt8++) {
        qa[kt8][0] = f2tf(Qst[qrow * APK + kt8 * 8 + tig]);
        qa[kt8][1] = f2tf(Qst[(qrow + 8) * APK + kt8 * 8 + tig]);
        qa[kt8][2] = f2tf(Qst[qrow * APK + kt8 * 8 + tig + 4]);
        qa[kt8][3] = f2tf(Qst[(qrow + 8) * APK + kt8 * 8 + tig + 4]);
    }

    float of[8][4] = {};
    float mrow[2] = {-1e30f, -1e30f};
    float lrow[2] = {0.f, 0.f};

    for (int kt = 0; kt < SS / 64; kt++) {
        __syncthreads();   // prev S/PV reads of Ks/Vs/Ps complete

        // K tile -> Ks[dk][key] (transposed), tf32
        {
            const float* Kt = Kg + (size_t)(kt * 64) * DD;
            const int ck = tid & 63, fq = tid >> 6;
            #pragma unroll
            for (int g2 = 0; g2 < 4; g2++) {
                const int f = fq * 4 + g2;
                float4 kv = *(const float4*)(Kt + (size_t)ck * DD + 4 * f);
                Ks[(4 * f + 0) * APK + ck] = f2tf(kv.x);
                Ks[(4 * f + 1) * APK + ck] = f2tf(kv.y);
                Ks[(4 * f + 2) * APK + ck] = f2tf(kv.z);
                Ks[(4 * f + 3) * APK + ck] = f2tf(kv.w);
            }
        }
        // V tile -> Vs[key][dk], tf32
        {
            const float* Vt = Vg + (size_t)(kt * 64) * DD;
            const int rv = tid >> 4, cv = (tid & 15) * 4;
            #pragma unroll
            for (int i = 0; i < 4; i++) {
                float4 vv = *(const float4*)(Vt + (size_t)(rv + 16 * i) * DD + cv);
                uint4 t = make_uint4(f2tf(vv.x), f2tf(vv.y), f2tf(vv.z), f2tf(vv.w));
                *(uint4*)&Vs[(rv + 16 * i) * APK + cv] = t;
            }
        }
        __syncthreads();

        // ---- S = Qs @ K^T ----
        float sf[8][4] = {};
        #pragma unroll
        for (int j = 0; j < 8; j++) {
            #pragma unroll
            for (int kt8 = 0; kt8 < 8; kt8++) {
                uint32_t bb[2];
                const int kr = kt8 * 8 + tig, nc = j * 8 + g;
                bb[0] = Ks[kr * APK + nc];
                bb[1] = Ks[(kr + 4) * APK + nc];
                mma8(sf[j], qa[kt8], bb);
            }
        }

        // ---- online softmax on C-fragments (rows g and g+8) ----
        float corr[2];
        #pragma unroll
        for (int i = 0; i < 2; i++) {
            float mx = -1e30f;
            #pragma unroll
            for (int j = 0; j < 8; j++)
                mx = fmaxf(mx, fmaxf(sf[j][2 * i], sf[j][2 * i + 1]));
            mx = fmaxf(mx, __shfl_xor_sync(0xffffffffu, mx, 1));
            mx = fmaxf(mx, __shfl_xor_sync(0xffffffffu, mx, 2));
            const float mn = fmaxf(mrow[i], mx);
            corr[i] = __expf(mrow[i] - mn);
            mrow[i] = mn;
            float rs = 0.f;
            #pragma unroll
            for (int j = 0; j < 8; j++) {
                sf[j][2 * i]     = __expf(sf[j][2 * i] - mn);
                sf[j][2 * i + 1] = __expf(sf[j][2 * i + 1] - mn);
                rs += sf[j][2 * i] + sf[j][2 * i + 1];
            }
            rs += __shfl_xor_sync(0xffffffffu, rs, 1);
            rs += __shfl_xor_sync(0xffffffffu, rs, 2);
            lrow[i] = lrow[i] * corr[i] + rs;
        }
        #pragma unroll
        for (int j = 0; j < 8; j++) {
            of[j][0] *= corr[0]; of[j][1] *= corr[0];
            of[j][2] *= corr[1]; of[j][3] *= corr[1];
        }

        // ---- P -> Ps (tf32) ----
        #pragma unroll
        for (int j = 0; j < 8; j++) {
            uint2 p01 = make_uint2(f2tf(sf[j][0]), f2tf(sf[j][1]));
            uint2 p23 = make_uint2(f2tf(sf[j][2]), f2tf(sf[j][3]));
            *(uint2*)&Ps[qrow * APK + j * 8 + 2 * tig]       = p01;
            *(uint2*)&Ps[(qrow + 8) * APK + j * 8 + 2 * tig] = p23;
        }
        __syncthreads();

        // ---- O += P @ V ----
        #pragma unroll
        for (int kt8 = 0; kt8 < 8; kt8++) {
            uint32_t pa[4];
            pa[0] = Ps[qrow * APK + kt8 * 8 + tig];
            pa[1] = Ps[(qrow + 8) * APK + kt8 * 8 + tig];
            pa[2] = Ps[qrow * APK + kt8 * 8 + tig + 4];
            pa[3] = Ps[(qrow + 8) * APK + kt8 * 8 + tig + 4];
            #pragma unroll
            for (int j = 0; j < 8; j++) {
                uint32_t bb[2];
                const int vr = kt8 * 8 + tig, nc = j * 8 + g;
                bb[0] = Vs[vr * APK + nc];
                bb[1] = Vs[(vr + 4) * APK + nc];
                mma8(of[j], pa, bb);
            }
        }
    }

    // ---- normalize + write context ----
    const float inv0 = 1.f / lrow[0], inv1 = 1.f / lrow[1];
    const size_t orow = (size_t)(b * SS + qt * 128 + qrow);
    #pragma unroll
    for (int j = 0; j < 8; j++) {
        const int n = h * 64 + j * 8 + 2 * tig;
        *(float2*)&g_ctx[orow * DD + n] =
            make_float2(of[j][0] * inv0, of[j][1] * inv0);
        *(float2*)&g_ctx[(orow + 8) * DD + n] =
            make_float2(of[j][2] * inv1, of[j][3] * inv1);
    }
}

// ---------------------------------------------------------------------------
extern "C" void kernel_launch(void* const* d_in, const int* in_sizes, int n_in,
                              void* d_out, int out_size)
{
    (void)in_sizes; (void)n_in; (void)out_size;
    const float* q  = (const float*)d_in[0];
    const float* k  = (const float*)d_in[1];
    const float* v  = (const float*)d_in[2];
    const float* wq = (const float*)d_in[3];
    const float* bq = (const float*)d_in[4];
    const float* wk = (const float*)d_in[5];
    const float* bk = (const float*)d_in[6];
    const float* wv = (const float*)d_in[7];
    const float* bv = (const float*)d_in[8];
    const float* wo = (const float*)d_in[9];
    const float* bo = (const float*)d_in[10];
    float* out = (float*)d_out;

    float *gq, *gk, *gv, *gctx;
    cudaGetSymbolAddress((void**)&gq,   g_Q);
    cudaGetSymbolAddress((void**)&gk,   g_K);
    cudaGetSymbolAddress((void**)&gv,   g_V);
    cudaGetSymbolAddress((void**)&gctx, g_ctx);

    const int ATTN_SMEM = 256 * APK * 4;   // 73728 B
    cudaFuncSetAttribute(attn_tc, cudaFuncAttributeMaxDynamicSharedMemorySize, ATTN_SMEM);

    dim3 ggrid(DD / 64, MM / 128);   // (16, 32) = 512 CTAs
    gemm_tc<<<ggrid, 256>>>(q, wq, bq, gq, MM, DD, DD);
    gemm_tc<<<ggrid, 256>>>(k, wk, bk, gk, MM, DD, DD);
    gemm_tc<<<ggrid, 256>>>(v, wv, bv, gv, MM, DD, DD);

    attn_tc<<<dim3(SS / 128, BB * HH), 256, ATTN_SMEM>>>();

    gemm_tc<<<ggrid, 256>>>(gctx, wo, bo, out, MM, DD, DD);
}